// round 4
// baseline (speedup 1.0000x reference)
#include <cuda_runtime.h>
#include <cuda_fp16.h>
#include <cstdint>

// Problem constants
#define M_TOKENS   2048
#define IN_FEAT    2048
#define OUT_FEAT   2048
#define TILE_B     16
#define C_BLOCKS   128
#define R_BLOCKS   128
#define K_BLOCKS   32

// Scratch (allocation-free rule: __device__ globals)
// x packed fp16, fragment-linear: [c (128)][token_group (128)][lane (32)][8 halves]
__device__ __half g_xh[(size_t)C_BLOCKS * (M_TOKENS / 16) * 32 * 8];   // 8 MB
// values packed fp16, B-fragment rows: [r][k][lane (32)][8 halves] (b0|b1 merged)
__device__ __half g_vh[(size_t)R_BLOCKS * K_BLOCKS * 32 * 8];          // 2 MB

// ---------------------------------------------------------------------------
// pack_x v3: smem-staged. CTA = (token group tg, 16 c-blocks).
// Phase 1: fully coalesced float2 loads of a [16 x 256] fp32 tile -> half smem
//          (row stride 264 halves -> conflict-free phase-2 reads).
// Phase 2: each thread assembles one 16B fragment row; 512B contiguous
//          stores per warp.
// ---------------------------------------------------------------------------
#define XROW 264   // halves per smem row

__global__ __launch_bounds__(256)
void pack_x_kernel(const float* __restrict__ x) {
    __shared__ __align__(16) __half sX[16 * XROW];   // ~8.25 KB

    const int tid = threadIdx.x;
    const int tg  = blockIdx.x >> 3;        // token group 0..127
    const int cg  = blockIdx.x & 7;         // c-block group 0..7 (16 c each)

    // Phase 1: 16 tokens x 256 floats, coalesced
    const float* gx = x + (size_t)(tg * 16) * IN_FEAT + cg * 256;
    #pragma unroll
    for (int i = 0; i < 8; i++) {
        int flat  = i * 256 + tid;          // 0..2047
        int token = flat >> 7;
        int cp    = flat & 127;
        float2 v  = *(const float2*)(gx + (size_t)token * IN_FEAT + cp * 2);
        *(__half2*)&sX[token * XROW + cp * 2] = __floats2half2_rn(v.x, v.y);
    }
    __syncthreads();

    // Phase 2: 512 fragments (16 c_local x 32 lanes); each thread does 2.
    #pragma unroll
    for (int f0 = 0; f0 < 2; f0++) {
        int f    = f0 * 256 + tid;
        int lane = f & 31;
        int cl   = f >> 5;
        __half2 h[4];
        #pragma unroll
        for (int p = 0; p < 4; p++) {
            int t  = (p & 1) * 8 + (lane >> 2);
            int jp = (p >> 1) * 4 + (lane & 3);
            h[p] = *(__half2*)&sX[t * XROW + cl * 16 + jp * 2];
        }
        int c = cg * 16 + cl;
        *(uint4*)(g_xh + (((size_t)c * 128 + tg) * 32 + lane) * 8) =
            *reinterpret_cast<uint4*>(h);
    }
}

// ---------------------------------------------------------------------------
// pack_v v3: one thread per (r,k,lane) -> 16B row holding both n-tiles.
// ---------------------------------------------------------------------------
__global__ __launch_bounds__(256)
void pack_v_kernel(const float* __restrict__ values) {
    int idx = blockIdx.x * blockDim.x + threadIdx.x;   // 131072
    if (idx >= R_BLOCKS * K_BLOCKS * 32) return;
    int lane = idx & 31;
    int k    = (idx >> 5) & 31;
    int r    = idx >> 10;
    int q    = lane & 3;
    int i    = lane >> 2;
    const float* vp = values + (((size_t)r * K_BLOCKS + k) * TILE_B + i) * TILE_B;
    float2 a0 = *(const float2*)(vp + 2 * q);          // nt=0, row i
    float2 a1 = *(const float2*)(vp + 2 * q + 8);
    const float* vp8 = vp + 8 * TILE_B;                // nt=1, row i+8
    float2 b0 = *(const float2*)(vp8 + 2 * q);
    float2 b1 = *(const float2*)(vp8 + 2 * q + 8);
    __half2 h[4];
    h[0] = __floats2half2_rn(a0.x, a0.y);
    h[1] = __floats2half2_rn(a1.x, a1.y);
    h[2] = __floats2half2_rn(b0.x, b0.y);
    h[3] = __floats2half2_rn(b1.x, b1.y);
    *(uint4*)(g_vh + (size_t)idx * 8) = *reinterpret_cast<uint4*>(h);
}

// ---------------------------------------------------------------------------
__device__ __forceinline__ void cp_async16(uint32_t saddr, const void* gaddr) {
    asm volatile("cp.async.cg.shared.global [%0], [%1], 16;\n"
                 :: "r"(saddr), "l"(gaddr));
}
__device__ __forceinline__ void cp_commit() {
    asm volatile("cp.async.commit_group;\n");
}
template <int N>
__device__ __forceinline__ void cp_wait() {
    asm volatile("cp.async.wait_group %0;\n" :: "n"(N));
}

__device__ __forceinline__ void mma16816(float* c, const uint4& a, const uint2& b) {
    asm volatile(
        "mma.sync.aligned.m16n8k16.row.col.f32.f16.f16.f32 "
        "{%0,%1,%2,%3}, {%4,%5,%6,%7}, {%8,%9}, {%0,%1,%2,%3};\n"
        : "+f"(c[0]), "+f"(c[1]), "+f"(c[2]), "+f"(c[3])
        : "r"(a.x), "r"(a.y), "r"(a.z), "r"(a.w), "r"(b.x), "r"(b.y));
}

// ---------------------------------------------------------------------------
// Main kernel: CTA = (256-token tile, one r). grid (8,128), 256 threads.
// values[r] (16 KB) smem-resident; A slabs (8 KB) in 3-stage cp.async ring,
// prefetch distance 2, one __syncthreads per k-iter. Static smem 40.1 KB.
// ---------------------------------------------------------------------------
#define STAGES 3
#define SLAB_HALVES (16 * 32 * 8)    // 8 KB per slab

__global__ __launch_bounds__(256)
void cms_main_kernel(const int* __restrict__ col_indices,
                     const float* __restrict__ bias,
                     float* __restrict__ out) {
    __shared__ __align__(16) __half sV[K_BLOCKS * 32 * 8];            // 16 KB
    __shared__ __align__(16) __half sA[STAGES][SLAB_HALVES];          // 24 KB
    __shared__ int s_col[K_BLOCKS];

    const int bx  = blockIdx.x;
    const int r   = blockIdx.y;
    const int tid = threadIdx.x;

    if (tid < K_BLOCKS) s_col[tid] = col_indices[r * K_BLOCKS + tid];
    __syncthreads();

    const uint32_t sv_base = (uint32_t)__cvta_generic_to_shared(sV);
    const uint32_t sa_base = (uint32_t)__cvta_generic_to_shared(&sA[0][0]);

    // Commit G0: V + slab0.  G1: slab1.
    {
        const __half* gv = g_vh + (size_t)r * (K_BLOCKS * 32 * 8);
        #pragma unroll
        for (int i = 0; i < 4; i++) {
            int chunk = i * 256 + tid;
            cp_async16(sv_base + chunk * 16, gv + chunk * 8);
        }
        const __half* ga0 = g_xh + ((size_t)s_col[0] * 128 + bx * 16) * 256;
        cp_async16(sa_base + tid * 16,        ga0 + tid * 8);
        cp_async16(sa_base + 4096 + tid * 16, ga0 + (tid + 256) * 8);
        cp_commit();
        const __half* ga1 = g_xh + ((size_t)s_col[1] * 128 + bx * 16) * 256;
        uint32_t sb1 = sa_base + SLAB_HALVES * 2;
        cp_async16(sb1 + tid * 16,        ga1 + tid * 8);
        cp_async16(sb1 + 4096 + tid * 16, ga1 + (tid + 256) * 8);
        cp_commit();
    }

    float acc[16];
    #pragma unroll
    for (int i = 0; i < 16; i++) acc[i] = 0.0f;

    const int w    = tid >> 5;
    const int lane = tid & 31;

    for (int k = 0; k < K_BLOCKS; k++) {
        if (k < K_BLOCKS - 1) cp_wait<1>(); else cp_wait<0>();
        __syncthreads();

        if (k + 2 < K_BLOCKS) {
            const __half* ga = g_xh + ((size_t)s_col[k + 2] * 128 + bx * 16) * 256;
            uint32_t sb = sa_base + ((k + 2) % STAGES) * (SLAB_HALVES * 2);
            cp_async16(sb + tid * 16,        ga + tid * 8);
            cp_async16(sb + 4096 + tid * 16, ga + (tid + 256) * 8);
            cp_commit();
        }

        const __half* Ab = sA[k % STAGES];
        uint4 a0 = *(const uint4*)&Ab[((w * 2 + 0) * 32 + lane) * 8];
        uint4 a1 = *(const uint4*)&Ab[((w * 2 + 1) * 32 + lane) * 8];
        uint4 vb = *(const uint4*)&sV[((size_t)k * 32 + lane) * 8];
        uint2 b0 = make_uint2(vb.x, vb.y);
        uint2 b1 = make_uint2(vb.z, vb.w);

        mma16816(acc + 0,  a0, b0);
        mma16816(acc + 4,  a0, b1);
        mma16816(acc + 8,  a1, b0);
        mma16816(acc + 12, a1, b1);
    }

    // Epilogue
    const int g = lane >> 2;
    const int q = lane & 3;
    #pragma unroll
    for (int mt = 0; mt < 2; mt++) {
        int token0 = bx * 256 + (w * 2 + mt) * 16;
        #pragma unroll
        for (int nt = 0; nt < 2; nt++) {
            int f = r * TILE_B + nt * 8 + q * 2;
            float bv0 = bias[f];
            float bv1 = bias[f + 1];
            const float* a = acc + (mt * 2 + nt) * 4;
            float* o0 = out + (size_t)(token0 + g) * OUT_FEAT + f;
            o0[0] = a[0] + bv0;
            o0[1] = a[1] + bv1;
            float* o1 = out + (size_t)(token0 + g + 8) * OUT_FEAT + f;
            o1[0] = a[2] + bv0;
            o1[1] = a[3] + bv1;
        }
    }
}

// ---------------------------------------------------------------------------
extern "C" void kernel_launch(void* const* d_in, const int* in_sizes, int n_in,
                              void* d_out, int out_size) {
    const float* x      = (const float*)d_in[0];
    const float* values = (const float*)d_in[1];
    const int*   col    = (const int*)d_in[2];
    const float* bias   = (const float*)d_in[3];
    float*       out    = (float*)d_out;

    (void)in_sizes; (void)n_in; (void)out_size;

    pack_x_kernel<<<128 * 8, 256>>>(x);
    pack_v_kernel<<<(R_BLOCKS * K_BLOCKS * 32) / 256, 256>>>(values);
    cms_main_kernel<<<dim3(M_TOKENS / 256, R_BLOCKS), 256>>>(col, bias, out);
}